// round 8
// baseline (speedup 1.0000x reference)
#include <cuda_runtime.h>
#include <cstdint>
#include <math.h>

// ---------------------------------------------------------------------------
// ImprovedGraphLSTMCell  (N=8192, K=8, H=512, X=512) — mma.sync tf32 (sm_100)
//
//  gemm_iou: C[8192,2048] = [x | hsum2] @ [[Wiou;Uiou] | [Wf;0]]  (K=1536)
//            cols: 0-511 i, 512-1023 o, 1024-1535 u, 1536-2047 wf_x
//  fgemm:    routed-A GEMM over (n,k) rows (K=1024), fused epilogue:
//            f = sigmoid(fmid + wfx + bf); c_agg = sum_k f*c_mail;
//            c = sig(i)tanh(u)+c_agg; h = sig(o)tanh(c) -> out (fully fused)
// ---------------------------------------------------------------------------

namespace {
constexpr int Nn  = 8192;
constexpr int Kmb = 8;
constexpr int Hh  = 512;
constexpr int Xx  = 512;
constexpr int NK  = Nn * Kmb;     // 65536
constexpr int H2v = 1024;

constexpr int BM = 128, BN = 256, BK = 32;
constexpr int A_EL = BM * BK;               // 4096 floats
constexpr int B_EL = BK * BN;               // 8192 floats
constexpr int STG_EL = A_EL + B_EL;         // 12288
constexpr int SMEM_BYTES = 3 * STG_EL * 4;  // 147456
}

// Scratch (device globals — no allocation allowed)
__device__ float g_ioufx[(size_t)Nn * 2048];   // 64 MB: i|o|u|wfx
__device__ float g_hsum2[(size_t)Nn * H2v];    // 32 MB (tf32)
__device__ float g_xt[(size_t)Nn * Xx];        // 16 MB (tf32)
__device__ float g_B[(size_t)1536 * 2048];     // 12 MB: [Wiou;Uiou | Wf;0] (tf32)
__device__ float g_uf[(size_t)H2v * Hh];       // 2 MB: Uf (tf32)

__device__ __forceinline__ uint32_t tf32b(float x) {
    uint32_t r;
    asm("cvt.rna.tf32.f32 %0, %1;" : "=r"(r) : "f"(x));
    return r;
}
__device__ __forceinline__ float to_tf32(float x) { return __uint_as_float(tf32b(x)); }
__device__ __forceinline__ float sigmoidf_(float x) { return 1.f / (1.f + __expf(-x)); }

__device__ __forceinline__ void mma8(float c[4],
                                     uint32_t a0, uint32_t a1, uint32_t a2, uint32_t a3,
                                     uint32_t b0, uint32_t b1) {
    asm volatile(
        "mma.sync.aligned.m16n8k8.row.col.f32.tf32.tf32.f32 "
        "{%0,%1,%2,%3}, {%4,%5,%6,%7}, {%8,%9}, {%0,%1,%2,%3};\n"
        : "+f"(c[0]), "+f"(c[1]), "+f"(c[2]), "+f"(c[3])
        : "r"(a0), "r"(a1), "r"(a2), "r"(a3), "r"(b0), "r"(b1));
}

__device__ __forceinline__ void cp16(uint32_t saddr, const void* gptr) {
    asm volatile("cp.async.cg.shared.global [%0], [%1], 16;\n" ::"r"(saddr), "l"(gptr));
}
#define CP_COMMIT() asm volatile("cp.async.commit_group;\n" ::: "memory")
#define CP_WAIT1()  asm volatile("cp.async.wait_group 1;\n" ::: "memory")

// ---------------------------------------------------------------------------
// Prep kernels
// ---------------------------------------------------------------------------
__global__ void cvt_k(const float4* __restrict__ in, float4* __restrict__ out, int n4) {
    int i = blockIdx.x * blockDim.x + threadIdx.x;
    if (i >= n4) return;
    float4 v = in[i];
    v.x = to_tf32(v.x); v.y = to_tf32(v.y);
    v.z = to_tf32(v.z); v.w = to_tf32(v.w);
    out[i] = v;
}

// Build g_B[1536 x 2048] = [[Wiou;Uiou] | [Wf;0]] and g_uf = tf32(Uf).
__global__ void prep_b(const float* __restrict__ Wiou, const float* __restrict__ Uiou,
                       const float* __restrict__ Wf,   const float* __restrict__ Uf) {
    const int NB4 = 1536 * 2048 / 4;           // 786432 float4s in g_B
    const int NU4 = H2v * Hh / 4;              // 131072 float4s in g_uf
    int i4 = blockIdx.x * blockDim.x + threadIdx.x;
    if (i4 < NB4) {
        int row = i4 / 512;                    // 2048/4 = 512 float4 per row
        int col = (i4 % 512) * 4;
        const float* src = nullptr;
        if (col < 1536) {
            src = (row < 512) ? Wiou + (size_t)row * 1536 + col
                              : Uiou + (size_t)(row - 512) * 1536 + col;
        } else if (row < 512) {
            src = Wf + (size_t)row * 512 + (col - 1536);
        }
        float4 v = src ? *(const float4*)src : make_float4(0.f, 0.f, 0.f, 0.f);
        v.x = to_tf32(v.x); v.y = to_tf32(v.y);
        v.z = to_tf32(v.z); v.w = to_tf32(v.w);
        *(float4*)(g_B + (size_t)i4 * 4) = v;
    } else if (i4 < NB4 + NU4) {
        int j4 = i4 - NB4;
        float4 v = *(const float4*)(Uf + (size_t)j4 * 4);
        v.x = to_tf32(v.x); v.y = to_tf32(v.y);
        v.z = to_tf32(v.z); v.w = to_tf32(v.w);
        *(float4*)(g_uf + (size_t)j4 * 4) = v;
    }
}

// Mailbox pre-reduction routed by edge label (tf32 output).
__global__ void prep_hsum(const float* __restrict__ hm, const float* __restrict__ el) {
    int idx = blockIdx.x * blockDim.x + threadIdx.x;
    if (idx >= Nn * Hh) return;
    int n = idx >> 9, h = idx & 511;
    const float* hp = hm + (size_t)n * Kmb * Hh + h;
    const float* ep = el + n * Kmb;
    float s0 = 0.f, s1 = 0.f;
#pragma unroll
    for (int k = 0; k < Kmb; k++) {
        float e = ep[k];
        float v = hp[(size_t)k * Hh];
        float ev = e * v;
        s1 += ev; s0 += v - ev;
    }
    g_hsum2[(size_t)n * H2v + h]      = to_tf32(s0);
    g_hsum2[(size_t)n * H2v + Hh + h] = to_tf32(s1);
}

// ---------------------------------------------------------------------------
// gemm_iou: C[8192,2048] = [x|hsum2] @ g_B   (K=1536, tf32 mma.sync)
// 256 thr, BM=128 BN=256 BK=32, warp grid 2x4, warp tile 64x64,
// 3-stage cp.async, XOR-swizzled smem (A: ch^(m&7); B: ch^((k&3)<<1)).
// ---------------------------------------------------------------------------
__global__ void __launch_bounds__(256, 1) gemm_iou_k() {
    extern __shared__ float smem[];
    const int tid = threadIdx.x, lane = tid & 31, wid = tid >> 5;
    const int g = lane >> 2, tg = lane & 3;
    const int wr = wid >> 2, wc = wid & 3;
    const int m0 = blockIdx.x * BM, n0 = blockIdx.y * BN;
    const uint32_t sb = (uint32_t)__cvta_generic_to_shared(smem);

    float acc[4][8][4];
#pragma unroll
    for (int a = 0; a < 4; a++)
#pragma unroll
        for (int b = 0; b < 8; b++)
#pragma unroll
            for (int c = 0; c < 4; c++) acc[a][b][c] = 0.f;

    const int cbA = tid & 7, rA0 = tid >> 3;                  // A: 8 thr/row
    const uint32_t swA = (uint32_t)((cbA ^ (rA0 & 7)) << 4);
    const int kB = tid >> 3, cbB = tid & 7;                   // B: 8 thr/row

    auto issue = [&](int kt, int st) {
        {   // A: [x | hsum2] rows m0+rA0+32i
            const float* srcA; int ldA;
            if (kt < 16) { srcA = g_xt + (size_t)(m0 + rA0) * 512 + kt * 32 + cbA * 4; ldA = 512; }
            else { srcA = g_hsum2 + (size_t)(m0 + rA0) * 1024 + (kt - 16) * 32 + cbA * 4; ldA = 1024; }
            uint32_t dst = sb + (uint32_t)(st * STG_EL + rA0 * 32) * 4 + swA;
#pragma unroll
            for (int i = 0; i < 4; i++)
                cp16(dst + (uint32_t)(i * 32 * 32) * 4, srcA + (size_t)(i * 32) * ldA);
        }
        {   // B: g_B rows kt*32+kB, 8 x 16B chunks each
            const float* srcB = g_B + (size_t)(kt * 32 + kB) * 2048 + n0;
            uint32_t dst = sb + (uint32_t)(st * STG_EL + A_EL + kB * 256) * 4;
#pragma unroll
            for (int i = 0; i < 8; i++) {
                int c = cbB + i * 8;
                cp16(dst + (uint32_t)((c ^ ((kB & 3) << 1)) << 4), srcB + c * 4);
            }
        }
    };

    auto compute = [&](int st) {
        const float* sA = smem + st * STG_EL;
        const float* sB = sA + A_EL;
#pragma unroll
        for (int ks = 0; ks < 4; ks++) {
            const int cA = ks * 2;
            uint32_t af[4][4], bf[8][2];
#pragma unroll
            for (int mi = 0; mi < 4; mi++) {
                const float* p = sA + (wr * 64 + mi * 16 + g) * 32 + tg;
                const int o0 = (cA ^ g) << 2, o1 = ((cA + 1) ^ g) << 2;
                af[mi][0] = __float_as_uint(p[o0]);
                af[mi][2] = __float_as_uint(p[o1]);
                af[mi][1] = __float_as_uint(p[256 + o0]);
                af[mi][3] = __float_as_uint(p[256 + o1]);
            }
            const float* q = sB + (ks * 8 + tg) * 256 + (g & 3);
#pragma unroll
            for (int ni = 0; ni < 8; ni++) {
                const int cX = ((wc * 16 + ni * 2 + (g >> 2)) ^ (tg << 1)) << 2;
                bf[ni][0] = __float_as_uint(q[cX]);
                bf[ni][1] = __float_as_uint(q[1024 + cX]);
            }
#pragma unroll
            for (int mi = 0; mi < 4; mi++)
#pragma unroll
                for (int ni = 0; ni < 8; ni++)
                    mma8(acc[mi][ni], af[mi][0], af[mi][1], af[mi][2], af[mi][3],
                         bf[ni][0], bf[ni][1]);
        }
    };

    const int KT = 48;
    issue(0, 0); CP_COMMIT();
    issue(1, 1); CP_COMMIT();
    for (int kt = 0; kt < KT; kt++) {
        CP_WAIT1();
        __syncthreads();
        if (kt + 2 < KT) issue(kt + 2, (kt + 2) % 3);
        CP_COMMIT();
        compute(kt % 3);
    }

#pragma unroll
    for (int mi = 0; mi < 4; mi++) {
#pragma unroll
        for (int ni = 0; ni < 8; ni++) {
            const int r0 = m0 + wr * 64 + mi * 16 + g;
            const int c0 = n0 + wc * 64 + ni * 8 + 2 * tg;
            *(float2*)(g_ioufx + (size_t)r0 * 2048 + c0) =
                make_float2(acc[mi][ni][0], acc[mi][ni][1]);
            *(float2*)(g_ioufx + (size_t)(r0 + 8) * 2048 + c0) =
                make_float2(acc[mi][ni][2], acc[mi][ni][3]);
        }
    }
}

// ---------------------------------------------------------------------------
// fgemm: rows = (n,k) pairs, K=1024 routed (A[.,0:512]=(1-e)h, A[.,512:]=e*h,
// built at fragment-load time from raw h_mail). Fused epilogue computes f,
// c_agg, and the full LSTM gates, writing out directly.
// ---------------------------------------------------------------------------
__global__ void __launch_bounds__(256, 1) fgemm_k(const float* __restrict__ hm,
                                                  const float* __restrict__ el,
                                                  const float* __restrict__ cm,
                                                  const float* __restrict__ biou,
                                                  const float* __restrict__ bfv,
                                                  float* __restrict__ out) {
    extern __shared__ float smem[];
    const int tid = threadIdx.x, lane = tid & 31, wid = tid >> 5;
    const int g = lane >> 2, tg = lane & 3;
    const int wr = wid >> 2, wc = wid & 3;
    const int m0 = blockIdx.x * BM;     // over NK rows
    const int n0 = blockIdx.y * BN;     // over H cols (0 or 256)
    const uint32_t sb = (uint32_t)__cvta_generic_to_shared(smem);

    float acc[4][8][4];
#pragma unroll
    for (int a = 0; a < 4; a++)
#pragma unroll
        for (int b = 0; b < 8; b++)
#pragma unroll
            for (int c = 0; c < 4; c++) acc[a][b][c] = 0.f;

    float e0[4], e1[4], s0[4], s1[4];
#pragma unroll
    for (int mi = 0; mi < 4; mi++) {
        const int r = m0 + wr * 64 + mi * 16 + g;
        e0[mi] = __ldg(el + r);
        e1[mi] = __ldg(el + r + 8);
    }

    const int cbA = tid & 7, rA0 = tid >> 3;
    const uint32_t swA = (uint32_t)((cbA ^ (rA0 & 7)) << 4);
    const int kB = tid >> 3, cbB = tid & 7;

    auto issue = [&](int kt, int st) {
        {   // A: raw h_mail rows, col folded mod 512
            const float* srcA = hm + (size_t)(m0 + rA0) * 512 + ((kt * 32) & 511) + cbA * 4;
            uint32_t dst = sb + (uint32_t)(st * STG_EL + rA0 * 32) * 4 + swA;
#pragma unroll
            for (int i = 0; i < 4; i++)
                cp16(dst + (uint32_t)(i * 32 * 32) * 4, srcA + (size_t)(i * 32) * 512);
        }
        {   // B = g_uf rows kt*32+kB
            const float* srcB = g_uf + (size_t)(kt * 32 + kB) * 512 + n0;
            uint32_t dst = sb + (uint32_t)(st * STG_EL + A_EL + kB * 256) * 4;
#pragma unroll
            for (int i = 0; i < 8; i++) {
                int c = cbB + i * 8;
                cp16(dst + (uint32_t)((c ^ ((kB & 3) << 1)) << 4), srcB + c * 4);
            }
        }
    };

    auto compute = [&](int st) {
        const float* sA = smem + st * STG_EL;
        const float* sB = sA + A_EL;
#pragma unroll
        for (int ks = 0; ks < 4; ks++) {
            const int cA = ks * 2;
            uint32_t af[4][4], bf[8][2];
#pragma unroll
            for (int mi = 0; mi < 4; mi++) {
                const float* p = sA + (wr * 64 + mi * 16 + g) * 32 + tg;
                const int o0 = (cA ^ g) << 2, o1 = ((cA + 1) ^ g) << 2;
                af[mi][0] = tf32b(s0[mi] * p[o0]);
                af[mi][2] = tf32b(s0[mi] * p[o1]);
                af[mi][1] = tf32b(s1[mi] * p[256 + o0]);
                af[mi][3] = tf32b(s1[mi] * p[256 + o1]);
            }
            const float* q = sB + (ks * 8 + tg) * 256 + (g & 3);
#pragma unroll
            for (int ni = 0; ni < 8; ni++) {
                const int cX = ((wc * 16 + ni * 2 + (g >> 2)) ^ (tg << 1)) << 2;
                bf[ni][0] = __float_as_uint(q[cX]);
                bf[ni][1] = __float_as_uint(q[1024 + cX]);
            }
#pragma unroll
            for (int mi = 0; mi < 4; mi++)
#pragma unroll
                for (int ni = 0; ni < 8; ni++)
                    mma8(acc[mi][ni], af[mi][0], af[mi][1], af[mi][2], af[mi][3],
                         bf[ni][0], bf[ni][1]);
        }
    };

    const int KT = 32;
    issue(0, 0); CP_COMMIT();
    issue(1, 1); CP_COMMIT();
    for (int kt = 0; kt < KT; kt++) {
        const bool hi = (kt >= 16);
#pragma unroll
        for (int mi = 0; mi < 4; mi++) {
            s0[mi] = hi ? e0[mi] : 1.f - e0[mi];
            s1[mi] = hi ? e1[mi] : 1.f - e1[mi];
        }
        CP_WAIT1();
        __syncthreads();
        if (kt + 2 < KT) issue(kt + 2, (kt + 2) % 3);
        CP_COMMIT();
        compute(kt % 3);
    }

    // Fused epilogue: f -> c_agg (shuffle over g) -> gates -> out.
#pragma unroll
    for (int mi = 0; mi < 4; mi++) {
        const int rbase = m0 + wr * 64 + mi * 16;   // 16 rows = nodes nA, nA+1
        const int nA = rbase >> 3;
#pragma unroll
        for (int ni = 0; ni < 8; ni++) {
            const int gc = n0 + wc * 64 + ni * 8 + 2 * tg;
            const float b0 = bfv[gc], b1 = bfv[gc + 1];
            const float wA0 = g_ioufx[(size_t)nA * 2048 + 1536 + gc];
            const float wA1 = g_ioufx[(size_t)nA * 2048 + 1536 + gc + 1];
            const float wB0 = g_ioufx[(size_t)(nA + 1) * 2048 + 1536 + gc];
            const float wB1 = g_ioufx[(size_t)(nA + 1) * 2048 + 1536 + gc + 1];
            const int rA = rbase + g;
            const float2 cA = *(const float2*)(cm + (size_t)rA * 512 + gc);
            const float2 cB = *(const float2*)(cm + (size_t)(rA + 8) * 512 + gc);
            float v0 = sigmoidf_(acc[mi][ni][0] + wA0 + b0) * cA.x;
            float v1 = sigmoidf_(acc[mi][ni][1] + wA1 + b1) * cA.y;
            float v2 = sigmoidf_(acc[mi][ni][2] + wB0 + b0) * cB.x;
            float v3 = sigmoidf_(acc[mi][ni][3] + wB1 + b1) * cB.y;
            // sum over the 8 rows of each node (lane bits 2..4 = g)
#pragma unroll
            for (int m = 4; m <= 16; m <<= 1) {
                v0 += __shfl_xor_sync(0xFFFFFFFFu, v0, m);
                v1 += __shfl_xor_sync(0xFFFFFFFFu, v1, m);
                v2 += __shfl_xor_sync(0xFFFFFFFFu, v2, m);
                v3 += __shfl_xor_sync(0xFFFFFFFFu, v3, m);
            }
            if (lane < 4) {
                // node nA, cols gc, gc+1
                {
                    const float* row = g_ioufx + (size_t)nA * 2048;
                    float i0 = sigmoidf_(row[gc] + biou[gc]);
                    float i1 = sigmoidf_(row[gc + 1] + biou[gc + 1]);
                    float o0v = sigmoidf_(row[512 + gc] + biou[512 + gc]);
                    float o1v = sigmoidf_(row[512 + gc + 1] + biou[512 + gc + 1]);
                    float u0 = tanhf(row[1024 + gc] + biou[1024 + gc]);
                    float u1 = tanhf(row[1024 + gc + 1] + biou[1024 + gc + 1]);
                    float c0v = i0 * u0 + v0, c1v = i1 * u1 + v1;
                    *(float2*)(out + (size_t)nA * 512 + gc) =
                        make_float2(o0v * tanhf(c0v), o1v * tanhf(c1v));
                    *(float2*)(out + (size_t)Nn * Hh + (size_t)nA * 512 + gc) =
                        make_float2(c0v, c1v);
                }
                // node nA+1
                {
                    const float* row = g_ioufx + (size_t)(nA + 1) * 2048;
                    float i0 = sigmoidf_(row[gc] + biou[gc]);
                    float i1 = sigmoidf_(row[gc + 1] + biou[gc + 1]);
                    float o0v = sigmoidf_(row[512 + gc] + biou[512 + gc]);
                    float o1v = sigmoidf_(row[512 + gc + 1] + biou[512 + gc + 1]);
                    float u0 = tanhf(row[1024 + gc] + biou[1024 + gc]);
                    float u1 = tanhf(row[1024 + gc + 1] + biou[1024 + gc + 1]);
                    float c0v = i0 * u0 + v2, c1v = i1 * u1 + v3;
                    *(float2*)(out + (size_t)(nA + 1) * 512 + gc) =
                        make_float2(o0v * tanhf(c0v), o1v * tanhf(c1v));
                    *(float2*)(out + (size_t)Nn * Hh + (size_t)(nA + 1) * 512 + gc) =
                        make_float2(c0v, c1v);
                }
            }
        }
    }
}

// ---------------------------------------------------------------------------
extern "C" void kernel_launch(void* const* d_in, const int* in_sizes, int n_in,
                              void* d_out, int out_size) {
    const float* x    = (const float*)d_in[0];
    const float* hm   = (const float*)d_in[1];
    const float* cm   = (const float*)d_in[2];
    const float* el   = (const float*)d_in[3];
    const float* Wiou = (const float*)d_in[4];
    const float* Wf   = (const float*)d_in[5];
    const float* Uiou = (const float*)d_in[6];
    const float* Uf   = (const float*)d_in[7];
    const float* biou = (const float*)d_in[8];
    const float* bfv  = (const float*)d_in[9];
    float* out = (float*)d_out;

    float* p_xt;
    cudaGetSymbolAddress((void**)&p_xt, g_xt);

    cudaFuncSetAttribute(gemm_iou_k, cudaFuncAttributeMaxDynamicSharedMemorySize, SMEM_BYTES);
    cudaFuncSetAttribute(fgemm_k,    cudaFuncAttributeMaxDynamicSharedMemorySize, SMEM_BYTES);

    // 0: x -> tf32
    {
        int n4 = Nn * Xx / 4;
        cvt_k<<<(n4 + 255) / 256, 256>>>((const float4*)x, (float4*)p_xt, n4);
    }
    // 1: weights -> g_B (concat, tf32) + g_uf (tf32)
    {
        int n4 = (1536 * 2048 + H2v * Hh) / 4;
        prep_b<<<(n4 + 255) / 256, 256>>>(Wiou, Uiou, Wf, Uf);
    }
    // 2: mailbox pre-reduction (tf32)
    prep_hsum<<<(Nn * Hh + 255) / 256, 256>>>(hm, el);
    // 3: merged iou+wfx GEMM (K=1536)
    gemm_iou_k<<<dim3(Nn / BM, 2048 / BN), 256, SMEM_BYTES>>>();
    // 4: fused f-GEMM + c_agg + gates -> out
    fgemm_k<<<dim3(NK / BM, Hh / BN), 256, SMEM_BYTES>>>(hm, el, cm, biou, bfv, out);
}